// round 9
// baseline (speedup 1.0000x reference)
#include <cuda_runtime.h>
#include <cstdint>

#define N_NODES 500000
#define N_EDGES 16000000
#define IN_DIM 17
#define GRID 888                  // 6 blocks/SM x 148 SMs -> all resident, safe grid barrier
#define TPB 256
#define NTHREADS (GRID * TPB)

__device__ float2 g_acc[N_NODES];   // {sum, count}
__device__ float  g_proj[N_NODES];  // x . w_l
__device__ float  g_base[N_NODES];  // b_l + x . w_r

// Software grid barrier state. Generation is monotonic across graph replays.
__device__ unsigned int g_cnt = 0;
__device__ volatile unsigned int g_gen = 0;

__device__ __forceinline__ void grid_sync()
{
    __syncthreads();
    __threadfence();                       // release: REDs/stores visible before arrive
    if (threadIdx.x == 0) {
        unsigned int my = g_gen;
        if (atomicAdd(&g_cnt, 1u) == GRID - 1) {
            g_cnt = 0;
            __threadfence();
            g_gen = my + 1;                // publish
        } else {
            while (g_gen == my) { __nanosleep(64); }
        }
    }
    __syncthreads();
    __threadfence();                       // acquire side
}

__global__ void __launch_bounds__(TPB, 6) fused_gnn(
    const float* __restrict__ x,
    const int*   __restrict__ ei,
    const float* __restrict__ w_l,
    const float* __restrict__ b_l,
    const float* __restrict__ w_r,
    const float* __restrict__ w_o,
    const float* __restrict__ b_o,
    float*       __restrict__ out)
{
    const int gtid = blockIdx.x * TPB + threadIdx.x;

    // ---- Phase 0: node projections + accumulator zeroing -------------------
    {
        float blv = __ldg(b_l);
        for (int n = gtid; n < N_NODES; n += NTHREADS) {
            const float* xr = x + (size_t)n * IN_DIM;
            float pl = 0.f, pr = 0.f;
#pragma unroll
            for (int i = 0; i < IN_DIM; i++) {
                float v = __ldg(xr + i);
                pl = fmaf(v, __ldg(w_l + i), pl);
                pr = fmaf(v, __ldg(w_r + i), pr);
            }
            g_proj[n] = pl;
            g_base[n] = pr + blv;
            g_acc[n]  = make_float2(0.f, 0.f);
        }
    }
    grid_sync();

    // ---- Phase 1: edge scatter (at the L1tex wavefront floor: 1 gather +
    // 1 spread RED per edge). 4 edges/thread/iter, best-measured granularity.
    {
        const int4* __restrict__ srcv = (const int4*)ei;
        const int4* __restrict__ dstv = (const int4*)(ei + N_EDGES);
        const float one = 1.0f;
        for (int q = gtid; q < N_EDGES / 4; q += NTHREADS) {
            int4 s = __ldcs(&srcv[q]);
            int4 d = __ldcs(&dstv[q]);
            // __ldcg: L2-coherent read of data written in phase 0 (no per-launch
            // L1 flush inside a persistent kernel).
            float m0 = __ldcg(&g_proj[s.x]);
            float m1 = __ldcg(&g_proj[s.y]);
            float m2 = __ldcg(&g_proj[s.z]);
            float m3 = __ldcg(&g_proj[s.w]);
            asm volatile("red.global.add.v2.f32 [%0], {%1, %2};"
                         :: "l"(&g_acc[d.x]), "f"(m0), "f"(one) : "memory");
            asm volatile("red.global.add.v2.f32 [%0], {%1, %2};"
                         :: "l"(&g_acc[d.y]), "f"(m1), "f"(one) : "memory");
            asm volatile("red.global.add.v2.f32 [%0], {%1, %2};"
                         :: "l"(&g_acc[d.z]), "f"(m2), "f"(one) : "memory");
            asm volatile("red.global.add.v2.f32 [%0], {%1, %2};"
                         :: "l"(&g_acc[d.w]), "f"(m3), "f"(one) : "memory");
        }
    }
    grid_sync();

    // ---- Phase 2: finalize -------------------------------------------------
    {
        float wo = __ldg(w_o), bo = __ldg(b_o);
        for (int n = gtid; n < N_NODES; n += NTHREADS) {
            float2 a = __ldcg(&g_acc[n]);
            float mean = a.x / fmaxf(a.y, 1.0f);
            float h = mean + __ldcg(&g_base[n]);
            h = (h > 0.f) ? h : expm1f(h);     // elu, alpha=1
            out[n] = fmaf(h, wo, bo);
        }
    }
}

extern "C" void kernel_launch(void* const* d_in, const int* in_sizes, int n_in,
                              void* d_out, int out_size)
{
    const float* x    = (const float*)d_in[0];
    const int*   ei   = (const int*)d_in[1];
    // d_in[2] = edge_weight: unused (faithful to reference / PyG SAGEConv)
    const float* w_l  = (const float*)d_in[3];
    const float* b_l  = (const float*)d_in[4];
    const float* w_r  = (const float*)d_in[5];
    const float* w_o  = (const float*)d_in[6];
    const float* b_o  = (const float*)d_in[7];
    float*       out  = (float*)d_out;

    (void)in_sizes; (void)n_in; (void)out_size;

    fused_gnn<<<GRID, TPB>>>(x, ei, w_l, b_l, w_r, w_o, b_o, out);
}